// round 17
// baseline (speedup 1.0000x reference)
#include <cuda_runtime.h>
#include <cuda_fp16.h>
#include <math.h>
#include <stdint.h>

// Problem dimensions (fixed)
#define SEQ   2048
#define DIN   11008
#define DOUT  4096
#define KR    4096

// ---------------------------------------------------------------------------
// Scratch (__device__ globals; no cudaMalloc allowed)
// ---------------------------------------------------------------------------
__device__ float  g_W [(size_t)DOUT * DIN];   // W' fp32 [o][i]
__device__ int8_t g_Q [(size_t)DOUT * DIN];   // quantized weights int8 [o][i]
__device__ __half g_A0[(size_t)DOUT * KR];    // (R^T * 64) hi  [o][k]
__device__ __half g_A1[(size_t)DOUT * KR];    // lo
__device__ __half g_B0[(size_t)DIN  * KR];    // ((w*S)^T * 64) hi [i][k]
__device__ __half g_B1[(size_t)DIN  * KR];    // lo
__device__ int8_t g_Xh[(size_t)SEQ  * DIN];   // x int16-hi byte [s][i]
__device__ int8_t g_Xl[(size_t)SEQ  * DIN];   // x int16-lo byte [s][i]
__device__ float  g_xs [SEQ];                 // per-token x scale
__device__ float  g_wscale[DOUT];
__device__ float  g_bias  [DOUT];
__device__ float  g_bpart [8 * DOUT];         // rot_bias partials

// ---------------------------------------------------------------------------
// PTX helpers
// ---------------------------------------------------------------------------
__device__ __forceinline__ uint32_t smem_u32(const void* p) {
    return (uint32_t)__cvta_generic_to_shared(p);
}
__device__ __forceinline__ void cp16(uint32_t s, const void* g) {
    asm volatile("cp.async.cg.shared.global [%0], [%1], 16;\n" :: "r"(s), "l"(g));
}
__device__ __forceinline__ void cp_commit() {
    asm volatile("cp.async.commit_group;" ::: "memory");
}
template<int N>
__device__ __forceinline__ void cp_wait() {
    asm volatile("cp.async.wait_group %0;" :: "n"(N) : "memory");
}
__device__ __forceinline__ void ldm4(uint32_t* r, uint32_t addr) {
    asm volatile("ldmatrix.sync.aligned.m8n8.x4.shared.b16 {%0,%1,%2,%3}, [%4];"
        : "=r"(r[0]), "=r"(r[1]), "=r"(r[2]), "=r"(r[3]) : "r"(addr));
}
__device__ __forceinline__ void mma16816(float* d, const uint32_t* a, uint32_t b0, uint32_t b1) {
    asm volatile("mma.sync.aligned.m16n8k16.row.col.f32.f16.f16.f32 "
        "{%0,%1,%2,%3}, {%4,%5,%6,%7}, {%8,%9}, {%0,%1,%2,%3};"
        : "+f"(d[0]), "+f"(d[1]), "+f"(d[2]), "+f"(d[3])
        : "r"(a[0]), "r"(a[1]), "r"(a[2]), "r"(a[3]), "r"(b0), "r"(b1));
}
__device__ __forceinline__ void mma_s8(int* d, const uint32_t* a, uint32_t b0, uint32_t b1) {
    asm volatile("mma.sync.aligned.m16n8k32.row.col.s32.s8.s8.s32 "
        "{%0,%1,%2,%3}, {%4,%5,%6,%7}, {%8,%9}, {%0,%1,%2,%3};"
        : "+r"(d[0]), "+r"(d[1]), "+r"(d[2]), "+r"(d[3])
        : "r"(a[0]), "r"(a[1]), "r"(a[2]), "r"(a[3]), "r"(b0), "r"(b1));
}

// ---------------------------------------------------------------------------
// Fused GEMM1: C = alpha * (A0@B0^T + A0@B1^T + A1@B0^T), one K-pass.
// Tile 128x128x32, 256 threads (2x4 warps of 64x32), 3-stage cp.async,
// 2 CTAs/SM. 64B smem rows, swizzle: chunk c at row r -> c ^ ((r>>1)&3).
// Inner loop interleaves A1-reload LDSMs under MMA cover (>=16 MMAs each).
// ---------------------------------------------------------------------------
#define H_STAGES   3
#define H_STAGE_SZ 32768                       // A0|A1|B0|B1 x 8KB
#define H_SMEM     (H_STAGES * H_STAGE_SZ + 1024)

__global__ __launch_bounds__(256, 2)
void gemm1_fused(const __half* __restrict__ A0, const __half* __restrict__ A1,
                 const __half* __restrict__ B0, const __half* __restrict__ B1,
                 int K, float* __restrict__ C, int ldc, float alpha)
{
    extern __shared__ char raw[];
    const uint32_t base = (smem_u32(raw) + 1023u) & ~1023u;

    const int tid  = threadIdx.x;
    const int lane = tid & 31, wid = tid >> 5;
    const int wr   = wid & 1, wc = wid >> 1;
    const int m0   = blockIdx.x * 128, n0 = blockIdx.y * 128;

    // loader: per matrix 512 16B chunks (128 rows x 4), 2/thread
    uint32_t so[2], go[2];
    #pragma unroll
    for (int j = 0; j < 2; j++) {
        int ch = tid + j * 256;
        int r = ch >> 2, c = ch & 3;
        so[j] = (uint32_t)(r * 64 + ((c ^ ((r >> 1) & 3)) << 4));
        go[j] = (uint32_t)(r * K + c * 8);     // halves
    }

    // ldmatrix per-lane byte offsets (proven R5-R11 pattern, BK=32)
    uint32_t aoff[2][4], boff[2][2];
    #pragma unroll
    for (int ks = 0; ks < 2; ks++) {
        #pragma unroll
        for (int mf = 0; mf < 4; mf++) {
            int r = wr * 64 + mf * 16 + (lane & 15);
            int c = ks * 2 + (lane >> 4);
            aoff[ks][mf] = (uint32_t)(r * 64 + ((c ^ ((r >> 1) & 3)) << 4));
        }
        #pragma unroll
        for (int nf = 0; nf < 2; nf++) {
            int r = wc * 32 + nf * 16 + (lane & 7) + ((lane >> 4) << 3);
            int c = ks * 2 + ((lane >> 3) & 1);
            boff[ks][nf] = (uint32_t)(r * 64 + ((c ^ ((r >> 1) & 3)) << 4));
        }
    }

    const int total = K >> 5;                  // one pass over K, all terms
    int lk = 0;
    auto issue = [&](int stage) {
        const __half* ga0 = A0 + (size_t)m0 * K + lk * 32;
        const __half* ga1 = A1 + (size_t)m0 * K + lk * 32;
        const __half* gb0 = B0 + (size_t)n0 * K + lk * 32;
        const __half* gb1 = B1 + (size_t)n0 * K + lk * 32;
        const uint32_t s0 = base + stage * H_STAGE_SZ;
        #pragma unroll
        for (int j = 0; j < 2; j++) {
            cp16(s0         + so[j], ga0 + go[j]);
            cp16(s0 +  8192 + so[j], ga1 + go[j]);
            cp16(s0 + 16384 + so[j], gb0 + go[j]);
            cp16(s0 + 24576 + so[j], gb1 + go[j]);
        }
        ++lk;
    };

    float acc[4][4][4];
    #pragma unroll
    for (int i = 0; i < 4; i++)
        #pragma unroll
        for (int j = 0; j < 4; j++)
            #pragma unroll
            for (int k = 0; k < 4; k++) acc[i][j][k] = 0.0f;

    #pragma unroll
    for (int s = 0; s < H_STAGES - 1; s++) {
        if (s < total) issue(s);
        cp_commit();
    }

    int st_c = 0, st_l = H_STAGES - 1;
    for (int i = 0; i < total; i++) {
        cp_wait<H_STAGES - 2>();
        __syncthreads();
        if (i + H_STAGES - 1 < total) issue(st_l);
        cp_commit();
        if (++st_l == H_STAGES) st_l = 0;

        const uint32_t s0 = base + st_c * H_STAGE_SZ;
        if (++st_c == H_STAGES) st_c = 0;

        #pragma unroll
        for (int ks = 0; ks < 2; ks++) {
            uint32_t af[4][4], b0f[2][4], b1f[2][4];
            #pragma unroll
            for (int mf = 0; mf < 4; mf++) ldm4(af[mf], s0 + aoff[ks][mf]);
            #pragma unroll
            for (int np = 0; np < 2; np++) {
                ldm4(b0f[np], s0 + 16384 + boff[ks][np]);
                ldm4(b1f[np], s0 + 24576 + boff[ks][np]);
            }
            // A0 products for mf=0,1 (16 MMAs)
            #pragma unroll
            for (int mf = 0; mf < 2; mf++)
                #pragma unroll
                for (int np = 0; np < 2; np++) {
                    mma16816(acc[mf][np * 2],     af[mf], b0f[np][0], b0f[np][1]);
                    mma16816(acc[mf][np * 2 + 1], af[mf], b0f[np][2], b0f[np][3]);
                    mma16816(acc[mf][np * 2],     af[mf], b1f[np][0], b1f[np][1]);
                    mma16816(acc[mf][np * 2 + 1], af[mf], b1f[np][2], b1f[np][3]);
                }
            // reload af[0..1] <- A1 (covered by the mf=2,3 MMAs below)
            ldm4(af[0], s0 + 8192 + aoff[ks][0]);
            ldm4(af[1], s0 + 8192 + aoff[ks][1]);
            // A0 products for mf=2,3 (16 MMAs)
            #pragma unroll
            for (int mf = 2; mf < 4; mf++)
                #pragma unroll
                for (int np = 0; np < 2; np++) {
                    mma16816(acc[mf][np * 2],     af[mf], b0f[np][0], b0f[np][1]);
                    mma16816(acc[mf][np * 2 + 1], af[mf], b0f[np][2], b0f[np][3]);
                    mma16816(acc[mf][np * 2],     af[mf], b1f[np][0], b1f[np][1]);
                    mma16816(acc[mf][np * 2 + 1], af[mf], b1f[np][2], b1f[np][3]);
                }
            // A1*B0 for mf=0,1 (8 MMAs), covering the af[2..3] reload
            #pragma unroll
            for (int mf = 0; mf < 2; mf++)
                #pragma unroll
                for (int np = 0; np < 2; np++) {
                    mma16816(acc[mf][np * 2],     af[mf], b0f[np][0], b0f[np][1]);
                    mma16816(acc[mf][np * 2 + 1], af[mf], b0f[np][2], b0f[np][3]);
                }
            // reload af[2..3] <- A1
            ldm4(af[2], s0 + 8192 + aoff[ks][2]);
            ldm4(af[3], s0 + 8192 + aoff[ks][3]);
            // A1*B0 for mf=2,3 (8 MMAs)
            #pragma unroll
            for (int mf = 2; mf < 4; mf++)
                #pragma unroll
                for (int np = 0; np < 2; np++) {
                    mma16816(acc[mf][np * 2],     af[mf], b0f[np][0], b0f[np][1]);
                    mma16816(acc[mf][np * 2 + 1], af[mf], b0f[np][2], b0f[np][3]);
                }
        }
    }

    const int ln4 = lane >> 2, lq = lane & 3;
    #pragma unroll
    for (int mf = 0; mf < 4; mf++) {
        #pragma unroll
        for (int h = 0; h < 2; h++) {
            const int row = m0 + wr * 64 + mf * 16 + ln4 + h * 8;
            float* crow = C + (size_t)row * ldc;
            #pragma unroll
            for (int nf = 0; nf < 4; nf++) {
                const int col = n0 + wc * 32 + nf * 8 + lq * 2;
                *(float2*)&crow[col] = make_float2(acc[mf][nf][h * 2] * alpha,
                                                   acc[mf][nf][h * 2 + 1] * alpha);
            }
        }
    }
}

// ---------------------------------------------------------------------------
// int8 GEMM (GEMM2): out[s][o] = ((256*Xh + Xl) @ Q^T) * rs[s]*cs[o] + cb[o]
// Tile 128x128, BK=128 bytes, 256 threads, 3-stage, 2 CTAs/SM (R13-proven).
// ---------------------------------------------------------------------------
#define S_STAGES   3
#define S_STAGE_SZ 32768
#define S_SMEM     (S_STAGES * S_STAGE_SZ + 1024)

__global__ __launch_bounds__(256, 2)
void gemm_s8(const int8_t* __restrict__ Xh, const int8_t* __restrict__ Xl,
             const int8_t* __restrict__ Q, int K,
             float* __restrict__ C, int ldc,
             const float* __restrict__ rs,
             const float* __restrict__ cs, const float* __restrict__ cb)
{
    extern __shared__ char raw[];
    const uint32_t base = (smem_u32(raw) + 1023u) & ~1023u;

    const int tid  = threadIdx.x;
    const int lane = tid & 31, wid = tid >> 5;
    const int wr   = wid & 1, wc = wid >> 1;
    const int m0   = blockIdx.x * 128, n0 = blockIdx.y * 128;

    uint32_t so[4], go[4];
    #pragma unroll
    for (int j = 0; j < 4; j++) {
        int ch = tid + j * 256;
        int r = ch >> 3, c = ch & 7;
        so[j] = (uint32_t)(r * 128 + ((c ^ (r & 7)) << 4));
        go[j] = (uint32_t)(r * K + c * 16);    // bytes
    }

    const int r7 = lane & 7;
    uint32_t arow[4], brow[2];
    #pragma unroll
    for (int mf = 0; mf < 4; mf++)
        arow[mf] = (uint32_t)((wr * 64 + mf * 16 + (lane & 15)) * 128);
    #pragma unroll
    for (int np = 0; np < 2; np++)
        brow[np] = (uint32_t)((wc * 32 + np * 16 + (lane & 15)) * 128);
    const int cx = lane >> 4;

    const int kpt   = K >> 7;
    const int total = 2 * kpt;
    int lt = 0, lk = 0;
    const int8_t* Aplanes[2] = { Xh, Xl };
    auto issue = [&](int stage) {
        const int8_t* ga = Aplanes[lt] + (size_t)m0 * K + lk * 128;
        const int8_t* gb = Q           + (size_t)n0 * K + lk * 128;
        const uint32_t sa = base + stage * S_STAGE_SZ;
        const uint32_t sb = sa + 16384;
        #pragma unroll
        for (int j = 0; j < 4; j++) {
            cp16(sa + so[j], ga + go[j]);
            cp16(sb + so[j], gb + go[j]);
        }
        if (++lk == kpt) { lk = 0; ++lt; }
    };

    int acc[4][4][4];
    #pragma unroll
    for (int i = 0; i < 4; i++)
        #pragma unroll
        for (int j = 0; j < 4; j++)
            #pragma unroll
            for (int k = 0; k < 4; k++) acc[i][j][k] = 0;

    #pragma unroll
    for (int s = 0; s < S_STAGES - 1; s++) {
        if (s < total) issue(s);
        cp_commit();
    }

    int st_c = 0, st_l = S_STAGES - 1;
    for (int i = 0; i < total; i++) {
        cp_wait<S_STAGES - 2>();
        __syncthreads();
        if (i + S_STAGES - 1 < total) issue(st_l);
        cp_commit();
        if (++st_l == S_STAGES) st_l = 0;

        const uint32_t sa = base + st_c * S_STAGE_SZ;
        const uint32_t sb = sa + 16384;
        if (++st_c == S_STAGES) st_c = 0;

        #pragma unroll
        for (int ks = 0; ks < 4; ks++) {
            const int kc = ks * 2;
            uint32_t af[4][4], bf[2][4];
            #pragma unroll
            for (int mf = 0; mf < 4; mf++)
                ldm4(af[mf], sa + arow[mf] + (uint32_t)(((kc + cx) ^ r7) << 4));
            #pragma unroll
            for (int np = 0; np < 2; np++)
                ldm4(bf[np], sb + brow[np] + (uint32_t)(((kc + cx) ^ r7) << 4));
            #pragma unroll
            for (int mf = 0; mf < 4; mf++)
                #pragma unroll
                for (int np = 0; np < 2; np++) {
                    mma_s8(acc[mf][np * 2],     af[mf], bf[np][0], bf[np][2]);
                    mma_s8(acc[mf][np * 2 + 1], af[mf], bf[np][1], bf[np][3]);
                }
        }

        if (i == kpt - 1) {
            #pragma unroll
            for (int a2 = 0; a2 < 4; a2++)
                #pragma unroll
                for (int b2 = 0; b2 < 4; b2++)
                    #pragma unroll
                    for (int c2 = 0; c2 < 4; c2++) acc[a2][b2][c2] <<= 8;
        }
    }

    const int ln4 = lane >> 2, lq = lane & 3;
    #pragma unroll
    for (int mf = 0; mf < 4; mf++) {
        #pragma unroll
        for (int h = 0; h < 2; h++) {
            const int row = m0 + wr * 64 + mf * 16 + ln4 + h * 8;
            const float srow = __ldg(&rs[row]);
            float* crow = C + (size_t)row * ldc;
            #pragma unroll
            for (int nf = 0; nf < 4; nf++) {
                const int col = n0 + wc * 32 + nf * 8 + lq * 2;
                float v0 = (float)acc[mf][nf][h * 2]     * (srow * __ldg(&cs[col]))     + __ldg(&cb[col]);
                float v1 = (float)acc[mf][nf][h * 2 + 1] * (srow * __ldg(&cs[col + 1])) + __ldg(&cb[col + 1]);
                *(float2*)&crow[col] = make_float2(v0, v1);
            }
        }
    }
}

// ---------------------------------------------------------------------------
// Prep: transpose + pre-scale + 2-way fp16 split, vectorized (R13-proven)
// ---------------------------------------------------------------------------
__global__ void tsplit2h(const float* __restrict__ src, int rows, int cols,
                         const float* __restrict__ colScale, float mul,
                         __half* __restrict__ o0, __half* __restrict__ o1)
{
    __shared__ float tsh[32][33];
    const int tid = threadIdx.x;
    const int c0 = blockIdx.x * 32, r0 = blockIdx.y * 32;

    {
        const int r = tid >> 3, c4 = tid & 7;
        float4 v = *(const float4*)&src[(size_t)(r0 + r) * cols + c0 + c4 * 4];
        tsh[c4 * 4 + 0][r] = v.x;
        tsh[c4 * 4 + 1][r] = v.y;
        tsh[c4 * 4 + 2][r] = v.z;
        tsh[c4 * 4 + 3][r] = v.w;
    }
    __syncthreads();

    {
        const int c = tid >> 3, r4 = tid & 7;
        const int cg = c0 + c;
        float s = mul;
        if (colScale) s *= colScale[cg];
        uint16_t hu[4], lu[4];
        #pragma unroll
        for (int i = 0; i < 4; i++) {
            float v = tsh[c][r4 * 4 + i] * s;
            __half hi = __float2half_rn(v);
            __half lo = __float2half_rn(v - __half2float(hi));
            hu[i] = *(uint16_t*)&hi;
            lu[i] = *(uint16_t*)&lo;
        }
        const size_t off = (size_t)cg * rows + r0 + r4 * 4;
        *(uint2*)&o0[off] = make_uint2((uint32_t)hu[0] | ((uint32_t)hu[1] << 16),
                                       (uint32_t)hu[2] | ((uint32_t)hu[3] << 16));
        *(uint2*)&o1[off] = make_uint2((uint32_t)lu[0] | ((uint32_t)lu[1] << 16),
                                       (uint32_t)lu[2] | ((uint32_t)lu[3] << 16));
    }
}

// ---------------------------------------------------------------------------
// Block reduce (max)
// ---------------------------------------------------------------------------
__device__ __forceinline__ float block_reduce_max(float v) {
    __shared__ float sh[32];
    int lane = threadIdx.x & 31;
    int wid  = threadIdx.x >> 5;
    #pragma unroll
    for (int o = 16; o; o >>= 1) v = fmaxf(v, __shfl_xor_sync(0xffffffffu, v, o));
    if (lane == 0) sh[wid] = v;
    __syncthreads();
    int nw = blockDim.x >> 5;
    v = (threadIdx.x < (unsigned)nw) ? sh[threadIdx.x] : 0.0f;
    if (wid == 0) {
        #pragma unroll
        for (int o = 16; o; o >>= 1) v = fmaxf(v, __shfl_xor_sync(0xffffffffu, v, o));
    }
    if (threadIdx.x == 0) sh[0] = v;
    __syncthreads();
    return sh[0];
}

// ---------------------------------------------------------------------------
// Fused per-token x quant: max -> scale -> int16 -> (hi,lo) int8 planes
// ---------------------------------------------------------------------------
__global__ void xquant_kernel(const float* __restrict__ x,
                              float* __restrict__ s_out,
                              int8_t* __restrict__ oh, int8_t* __restrict__ ol)
{
    const int row = blockIdx.x;
    const float4* p = (const float4*)(x + (size_t)row * DIN);
    float m = 0.0f;
    for (int i = threadIdx.x; i < DIN / 4; i += blockDim.x) {
        float4 v = p[i];
        m = fmaxf(m, fmaxf(fmaxf(fabsf(v.x), fabsf(v.y)), fmaxf(fabsf(v.z), fabsf(v.w))));
    }
    m = block_reduce_max(m);
    const float sc  = fmaxf(__fdiv_rn(m, 32512.0f), 1e-20f);
    const float inv = __fdiv_rn(1.0f, sc);
    if (threadIdx.x == 0) s_out[row] = sc;

    uint32_t* ph = (uint32_t*)(oh + (size_t)row * DIN);
    uint32_t* pl = (uint32_t*)(ol + (size_t)row * DIN);
    for (int i = threadIdx.x; i < DIN / 4; i += blockDim.x) {
        float4 v = p[i];
        int iv[4];
        iv[0] = (int)fminf(fmaxf(rintf(v.x * inv), -32512.0f), 32512.0f);
        iv[1] = (int)fminf(fmaxf(rintf(v.y * inv), -32512.0f), 32512.0f);
        iv[2] = (int)fminf(fmaxf(rintf(v.z * inv), -32512.0f), 32512.0f);
        iv[3] = (int)fminf(fmaxf(rintf(v.w * inv), -32512.0f), 32512.0f);
        uint32_t hw = 0, lw = 0;
        #pragma unroll
        for (int j = 0; j < 4; j++) {
            int h = (iv[j] + 128) >> 8;
            int l = iv[j] - (h << 8);
            hw |= ((uint32_t)(uint8_t)(int8_t)h) << (j * 8);
            lw |= ((uint32_t)(uint8_t)(int8_t)l) << (j * 8);
        }
        ph[i] = hw;
        pl[i] = lw;
    }
}

// ---------------------------------------------------------------------------
// Fused per-row weight quant: max -> scale -> int8
// ---------------------------------------------------------------------------
__global__ void wquant_kernel(const float* __restrict__ W,
                              float* __restrict__ scale,
                              int8_t* __restrict__ q)
{
    const int row = blockIdx.x;
    const float4* p = (const float4*)(W + (size_t)row * DIN);
    float m = 0.0f;
    for (int i = threadIdx.x; i < DIN / 4; i += blockDim.x) {
        float4 v = p[i];
        m = fmaxf(m, fmaxf(fmaxf(fabsf(v.x), fabsf(v.y)), fmaxf(fabsf(v.z), fabsf(v.w))));
    }
    m = block_reduce_max(m);
    const float s = fmaxf(__fdiv_rn(m, 127.0f), 1e-8f);
    if (threadIdx.x == 0) scale[row] = s;

    uint32_t* pq = (uint32_t*)(q + (size_t)row * DIN);
    for (int i = threadIdx.x; i < DIN / 4; i += blockDim.x) {
        float4 v = p[i];
        int qx = (int)fminf(fmaxf(rintf(__fdiv_rn(v.x, s)), -128.0f), 127.0f);
        int qy = (int)fminf(fmaxf(rintf(__fdiv_rn(v.y, s)), -128.0f), 127.0f);
        int qz = (int)fminf(fmaxf(rintf(__fdiv_rn(v.z, s)), -128.0f), 127.0f);
        int qw = (int)fminf(fmaxf(rintf(__fdiv_rn(v.w, s)), -128.0f), 127.0f);
        pq[i] = ((uint32_t)(uint8_t)(int8_t)qx)
              | ((uint32_t)(uint8_t)(int8_t)qy << 8)
              | ((uint32_t)(uint8_t)(int8_t)qz << 16)
              | ((uint32_t)(uint8_t)(int8_t)qw << 24);
    }
}

// ---------------------------------------------------------------------------
// Rotated bias, parallel: partials over 8 K-slices, then deterministic reduce
// ---------------------------------------------------------------------------
__global__ void rot_bias_part(const float* __restrict__ R,
                              const float* __restrict__ bias,
                              float* __restrict__ part)
{
    const int o  = blockIdx.x * blockDim.x + threadIdx.x;
    const int k0 = blockIdx.y * (KR / 8);
    float acc = 0.0f;
    for (int k = k0; k < k0 + KR / 8; k++)
        acc = fmaf(R[(size_t)k * DOUT + o], __ldg(&bias[k]), acc);
    part[blockIdx.y * DOUT + o] = acc;
}
__global__ void rot_bias_reduce(const float* __restrict__ part,
                                float* __restrict__ out)
{
    const int o = blockIdx.x * blockDim.x + threadIdx.x;
    float acc = 0.0f;
    #pragma unroll
    for (int j = 0; j < 8; j++) acc += part[j * DOUT + o];
    out[o] = acc;
}

// ---------------------------------------------------------------------------
// 16-bit per-token fake-quant, in place
// ---------------------------------------------------------------------------
__global__ void out_quant_kernel(float* __restrict__ out)
{
    const int s = blockIdx.x;
    float* p = out + (size_t)s * DOUT;
    float m = 0.0f;
    for (int i = threadIdx.x * 4; i < DOUT; i += blockDim.x * 4) {
        float4 v = *(const float4*)&p[i];
        m = fmaxf(m, fmaxf(fmaxf(fabsf(v.x), fabsf(v.y)), fmaxf(fabsf(v.z), fabsf(v.w))));
    }
    m = block_reduce_max(m);
    const float sc = fmaxf(__fdiv_rn(m, 32767.0f), 1e-8f);
    for (int i = threadIdx.x * 4; i < DOUT; i += blockDim.x * 4) {
        float4 v = *(const float4*)&p[i];
        v.x = fminf(fmaxf(rintf(__fdiv_rn(v.x, sc)), -32768.0f), 32767.0f) * sc;
        v.y = fminf(fmaxf(rintf(__fdiv_rn(v.y, sc)), -32768.0f), 32767.0f) * sc;
        v.z = fminf(fmaxf(rintf(__fdiv_rn(v.z, sc)), -32768.0f), 32767.0f) * sc;
        v.w = fminf(fmaxf(rintf(__fdiv_rn(v.w, sc)), -32768.0f), 32767.0f) * sc;
        *(float4*)&p[i] = v;
    }
}

// ---------------------------------------------------------------------------
// Launch
// ---------------------------------------------------------------------------
extern "C" void kernel_launch(void* const* d_in, const int* in_sizes, int n_in,
                              void* d_out, int out_size)
{
    const float* d_x = (const float*)d_in[0];
    const float* d_w = (const float*)d_in[1];
    const float* d_b = (const float*)d_in[2];
    const float* d_S = (const float*)d_in[3];
    const float* d_R = (const float*)d_in[4];
    float*       d_o = (float*)d_out;

    float *gW, *gws, *gbias, *gxs, *gbp;
    __half *gA0, *gA1, *gB0, *gB1;
    int8_t *gQ, *gXh, *gXl;
    cudaGetSymbolAddress((void**)&gW,   g_W);
    cudaGetSymbolAddress((void**)&gQ,   g_Q);
    cudaGetSymbolAddress((void**)&gA0,  g_A0);
    cudaGetSymbolAddress((void**)&gA1,  g_A1);
    cudaGetSymbolAddress((void**)&gB0,  g_B0);
    cudaGetSymbolAddress((void**)&gB1,  g_B1);
    cudaGetSymbolAddress((void**)&gXh,  g_Xh);
    cudaGetSymbolAddress((void**)&gXl,  g_Xl);
    cudaGetSymbolAddress((void**)&gxs,  g_xs);
    cudaGetSymbolAddress((void**)&gws,  g_wscale);
    cudaGetSymbolAddress((void**)&gbias, g_bias);
    cudaGetSymbolAddress((void**)&gbp,  g_bpart);

    cudaFuncSetAttribute(gemm1_fused, cudaFuncAttributeMaxDynamicSharedMemorySize, H_SMEM);
    cudaFuncSetAttribute(gemm_s8,     cudaFuncAttributeMaxDynamicSharedMemorySize, S_SMEM);

    // 1) rotated bias (parallel partials + deterministic reduce)
    rot_bias_part<<<dim3(DOUT / 256, 8), 256>>>(d_R, d_b, gbp);
    rot_bias_reduce<<<DOUT / 256, 256>>>(gbp, gbias);

    // 2) prep: fp16 splits for GEMM1; fused per-token x quant for GEMM2
    tsplit2h<<<dim3(DOUT / 32, KR / 32), 256>>>(d_R, KR, DOUT, nullptr, 64.0f, gA0, gA1);
    tsplit2h<<<dim3(DIN / 32, KR / 32),  256>>>(d_w, KR, DIN,  d_S,    64.0f, gB0, gB1);
    xquant_kernel<<<SEQ, 256>>>(d_x, gxs, gXh, gXl);

    // 3) GEMM1 fused: W' = (A0+A1)(B0+B1) keeping 3 significant products,
    //    one K-pass, alpha = 2^-12 un-scale
    {
        dim3 grid(DOUT / 128, DIN / 128);
        gemm1_fused<<<grid, 256, H_SMEM>>>(gA0, gA1, gB0, gB1, KR, gW, DIN, 1.0f / 4096.0f);
    }

    // 4) fused weight rowmax + int8 quantize
    wquant_kernel<<<DOUT, 256>>>(gW, gws, gQ);

    // 5) GEMM2 (int8, exact): out = (x16 @ q^T) * s_tok*s_o + b'
    {
        dim3 grid(SEQ / 128, DOUT / 128);
        gemm_s8<<<grid, 256, S_SMEM>>>(gXh, gXl, gQ, DIN, d_o, DOUT, gxs, gws, gbias);
    }

    // 6) 16-bit per-token fake-quant in place
    out_quant_kernel<<<SEQ, 256>>>(d_o);
}